// round 5
// baseline (speedup 1.0000x reference)
#include <cuda_runtime.h>
#include <cuda_bf16.h>
#include <stdint.h>
#include <math.h>

#define NB   64
#define NQ   900
#define NT   128
#define NCLS 91
#define LK   16    // per-column candidate list depth

typedef unsigned long long u64;
typedef unsigned int       u32;

// monotonic float -> uint mapping (ascending)
__device__ __forceinline__ u32 f2ord(float f) {
    u32 u = __float_as_uint(f);
    return (u & 0x80000000u) ? ~u : (u | 0x80000000u);
}
__device__ __forceinline__ u64 umin64(u64 a, u64 b) { return a < b ? a : b; }
__device__ __forceinline__ u64 umax64(u64 a, u64 b) { return a < b ? b : a; }

// ---------------------------------------------------------------------------
// Kernel 1: cost matrix.  8 warps x 2 rows each; warp-level softmax.
// ---------------------------------------------------------------------------
__global__ void __launch_bounds__(256) cost_kernel(
    const float* __restrict__ logits,   // [B,Q,91]
    const float* __restrict__ pboxes,   // [B,Q,4]
    const int*   __restrict__ labels,   // [B,T]
    const float* __restrict__ tboxes,   // [B,T,4]
    float* __restrict__ Cout)           // [B,Q,T]
{
    const int b    = blockIdx.y;
    const int tid  = threadIdx.x;
    const int lane = tid & 31;
    const int wid  = tid >> 5;

    __shared__ float4 s_tb[NT];
    __shared__ float4 s_tx[NT];
    __shared__ float  s_ta[NT];
    __shared__ int    s_lab[NT];
    __shared__ float  s_exp[8][92];

    if (tid < NT) {
        const float* tb = tboxes + ((size_t)b * NT + tid) * 4;
        float cx = tb[0], cy = tb[1], w = tb[2], h = tb[3];
        s_tb[tid] = make_float4(cx, cy, w, h);
        float x0 = cx - 0.5f * w, y0 = cy - 0.5f * h;
        float x1 = cx + 0.5f * w, y1 = cy + 0.5f * h;
        s_tx[tid] = make_float4(x0, y0, x1, y1);
        s_ta[tid] = (x1 - x0) * (y1 - y0);
        s_lab[tid] = labels[b * NT + tid];
    }
    __syncthreads();

    #pragma unroll
    for (int rr = 0; rr < 2; rr++) {
        int q = blockIdx.x * 16 + rr * 8 + wid;
        if (q >= NQ) continue;

        const float* lr = logits + ((size_t)b * NQ + q) * NCLS;
        float l0 = lr[lane];
        float l1 = lr[lane + 32];
        float l2 = (lane + 64 < NCLS) ? lr[lane + 64] : -INFINITY;
        float m = fmaxf(fmaxf(l0, l1), l2);
        #pragma unroll
        for (int o = 16; o; o >>= 1) m = fmaxf(m, __shfl_xor_sync(0xffffffffu, m, o));
        float e0 = expf(l0 - m), e1 = expf(l1 - m);
        float e2 = (lane + 64 < NCLS) ? expf(l2 - m) : 0.0f;
        float ssum = e0 + e1 + e2;
        #pragma unroll
        for (int o = 16; o; o >>= 1) ssum += __shfl_xor_sync(0xffffffffu, ssum, o);
        s_exp[wid][lane] = e0;
        s_exp[wid][lane + 32] = e1;
        if (lane + 64 < NCLS) s_exp[wid][lane + 64] = e2;
        __syncwarp();
        float inv = 1.0f / ssum;

        const float* pbp = pboxes + ((size_t)b * NQ + q) * 4;
        float pcx = pbp[0], pcy = pbp[1], pw = pbp[2], ph = pbp[3];
        float px0 = pcx - 0.5f * pw, py0 = pcy - 0.5f * ph;
        float px1 = pcx + 0.5f * pw, py1 = pcy + 0.5f * ph;
        float pa  = (px1 - px0) * (py1 - py0);

        float cst[4];
        #pragma unroll
        for (int r = 0; r < 4; r++) {
            int t = (lane << 2) | r;
            float4 tb = s_tb[t];
            float4 tx = s_tx[t];
            float pl  = s_exp[wid][s_lab[t]] * inv;
            float l1c = fabsf(pcx - tb.x) + fabsf(pcy - tb.y)
                      + fabsf(pw - tb.z) + fabsf(ph - tb.w);
            float ix0 = fmaxf(px0, tx.x), iy0 = fmaxf(py0, tx.y);
            float ix1 = fminf(px1, tx.z), iy1 = fminf(py1, tx.w);
            float inter = fmaxf(ix1 - ix0, 0.0f) * fmaxf(iy1 - iy0, 0.0f);
            float uni   = pa + s_ta[t] - inter;
            float iou   = inter / uni;
            float cx0 = fminf(px0, tx.x), cy0 = fminf(py0, tx.y);
            float cx1 = fmaxf(px1, tx.z), cy1 = fmaxf(py1, tx.w);
            float ac  = fmaxf(cx1 - cx0, 0.0f) * fmaxf(cy1 - cy0, 0.0f);
            float giou = iou - (ac - uni) / ac;
            cst[r] = -pl + 5.0f * l1c - 2.0f * giou;
        }

        float* crow = Cout + ((size_t)b * NQ + q) * NT;
        *(float4*)(crow + (lane << 2)) = make_float4(cst[0], cst[1], cst[2], cst[3]);
    }
}

// ---------------------------------------------------------------------------
// Kernel 2: greedy via per-column sorted top-16 candidate lists (SMEM) +
// single-warp sequential loop with register-resident column heads.
// ---------------------------------------------------------------------------
__global__ void __launch_bounds__(256) greedy_kernel(
    const float* __restrict__ Cmat,    // [B,Q,T] row-major
    float* __restrict__ out)
{
    const int b    = blockIdx.x;
    const int tid  = threadIdx.x;
    const int lane = tid & 31;
    const int wid  = tid >> 5;
    const float* __restrict__ Cb = Cmat + (size_t)b * NQ * NT;

    __shared__ u64 s_list[NT][32];     // staging: [0..15] asc (half0), [16..31] desc (half1)
    __shared__ u32 s_rowdead[32];      // 900-bit bitmap
    __shared__ int s_src[NT], s_tgt[NT];

    // ---- phase 1: each of 256 threads builds sorted top-16 of a half-column ----
    {
        const int c    = tid & 127;
        const int half = tid >> 7;
        const int q0   = half ? 448 : 0;
        const int q1   = half ? NQ  : 448;

        u64 lst[LK];
        #pragma unroll
        for (int s = 0; s < LK; s++) lst[s] = ~0ull;

        for (int qb = q0; qb < q1; qb += 16) {
            float v[16];
            #pragma unroll
            for (int x = 0; x < 16; x++) {
                int q = qb + x;
                v[x] = (q < q1) ? Cb[q * NT + c] : 0.0f;
            }
            #pragma unroll
            for (int x = 0; x < 16; x++) {
                int q = qb + x;
                if (q < q1) {
                    u64 k = ((u64)f2ord(v[x]) << 18) | ((u32)q << 8) | (u32)c;
                    if (k < lst[LK - 1]) {
                        lst[LK - 1] = k;
                        #pragma unroll
                        for (int s = LK - 1; s > 0; s--) {
                            u64 a = lst[s - 1], bb = lst[s];
                            lst[s - 1] = umin64(a, bb);
                            lst[s]     = umax64(a, bb);
                        }
                    }
                }
            }
        }
        if (half == 0) {
            #pragma unroll
            for (int s = 0; s < LK; s++) s_list[c][s] = lst[s];
        } else {
            #pragma unroll
            for (int s = 0; s < LK; s++) s_list[c][31 - s] = lst[s];
        }
    }
    if (tid < 32) s_rowdead[tid] = 0u;
    __syncthreads();

    // ---- phase 2: bitonic halver + merge -> sorted 16 smallest in [0..15] ----
    if (tid < NT) {
        const int c = tid;
        #pragma unroll
        for (int s = 0; s < 16; s++) {
            u64 a = s_list[c][s], bb = s_list[c][s + 16];
            s_list[c][s] = umin64(a, bb);
        }
        #pragma unroll
        for (int j = 8; j > 0; j >>= 1) {
            #pragma unroll
            for (int s = 0; s < 16; s++) {
                if ((s & j) == 0) {
                    u64 a = s_list[c][s], bb = s_list[c][s | j];
                    s_list[c][s]     = umin64(a, bb);
                    s_list[c][s | j] = umax64(a, bb);
                }
            }
        }
    }
    __syncthreads();

    // ---- phase 3: warp 0 runs all 128 steps; other warps exit ----
    if (wid != 0) return;

    u64 ck[4];     // column heads: col = r*32 + lane
    int pos[4];
    #pragma unroll
    for (int r = 0; r < 4; r++) {
        ck[r]  = s_list[r * 32 + lane][0];
        pos[r] = 1;
    }

    for (int t = 0; t < NT; t++) {
        u64 m = umin64(umin64(ck[0], ck[1]), umin64(ck[2], ck[3]));
        #pragma unroll
        for (int o = 16; o; o >>= 1)
            m = umin64(m, __shfl_xor_sync(0xffffffffu, m, o));

        const int i = (int)((m >> 8) & 0x3FFu);
        const int j = (int)(m & 0xFFu);
        if (lane == 0) {
            s_src[t] = i;
            s_tgt[t] = j;
            s_rowdead[i >> 5] |= (1u << (i & 31));
        }
        if (t == NT - 1) break;

        // kill column j; advance columns whose head row just died
        u32 exh = 0;
        #pragma unroll
        for (int r = 0; r < 4; r++) {
            if (ck[r] == m) { ck[r] = ~0ull; continue; }
            if (ck[r] != ~0ull && (int)((ck[r] >> 8) & 0x3FFu) == i) {
                const int c = r * 32 + lane;
                int p = pos[r];
                bool found = false;
                while (p < LK) {
                    u64 e = s_list[c][p]; p++;
                    int q = (int)((e >> 8) & 0x3FFu);
                    if (q != i && !((s_rowdead[q >> 5] >> (q & 31)) & 1u)) {
                        ck[r] = e; pos[r] = p; found = true; break;
                    }
                }
                if (!found) { exh |= (1u << r); pos[r] = LK; }
            }
        }

        // rare: candidate list exhausted -> warp-cooperative full column rescan
        if (__ballot_sync(0xffffffffu, exh != 0)) {
            #pragma unroll
            for (int r = 0; r < 4; r++) {
                u32 mask = __ballot_sync(0xffffffffu, (exh >> r) & 1u);
                while (mask) {
                    const int sl = __ffs(mask) - 1;
                    mask &= mask - 1;
                    const int c = r * 32 + sl;
                    u64 best = ~0ull;
                    for (int q = lane; q < NQ; q += 32) {
                        if (q == i) continue;
                        if ((s_rowdead[q >> 5] >> (q & 31)) & 1u) continue;
                        u64 k = ((u64)f2ord(Cb[q * NT + c]) << 18) | ((u32)q << 8) | (u32)c;
                        best = umin64(best, k);
                    }
                    #pragma unroll
                    for (int o = 16; o; o >>= 1)
                        best = umin64(best, __shfl_xor_sync(0xffffffffu, best, o));
                    if (lane == sl) ck[r] = best;
                }
            }
        }
        __syncwarp();
    }

    __syncwarp();
    #pragma unroll
    for (int r = 0; r < 4; r++) {
        int t = r * 32 + lane;
        out[b * NT + t]           = (float)s_src[t];
        out[NB * NT + b * NT + t] = (float)s_tgt[t];
    }
}

// ---------------------------------------------------------------------------
extern "C" void kernel_launch(void* const* d_in, const int* in_sizes, int n_in,
                              void* d_out, int out_size) {
    const float* logits = (const float*)d_in[0];   // [64,900,91]
    const float* pboxes = (const float*)d_in[1];   // [64,900,4]
    const int*   labels = (const int*)d_in[2];     // [64,128]
    const float* tboxes = (const float*)d_in[3];   // [64,128,4]
    float* out = (float*)d_out;

    float* Cout = out + 2 * NB * NT;   // C follows the two index blocks

    dim3 grid1((NQ + 15) / 16, NB);
    cost_kernel<<<grid1, 256>>>(logits, pboxes, labels, tboxes, Cout);

    greedy_kernel<<<NB, 256>>>(Cout, out);
}

// round 6
// speedup vs baseline: 1.0366x; 1.0366x over previous
#include <cuda_runtime.h>
#include <cuda_bf16.h>
#include <stdint.h>
#include <math.h>

#define NB   64
#define NQ   900
#define NT   128
#define NCLS 91
#define LK   16
#define CTS  912   // padded transposed column stride

typedef unsigned long long u64;
typedef unsigned int       u32;

// Transposed cost copy: g_Ct[b][col][q] (column-contiguous, for fallback rescans)
__device__ float g_Ct[(size_t)NB * NT * CTS];

__device__ __forceinline__ u32 f2ord(float f) {
    u32 u = __float_as_uint(f);
    return (u & 0x80000000u) ? ~u : (u | 0x80000000u);
}
__device__ __forceinline__ u64 umin64(u64 a, u64 b) { return a < b ? a : b; }
__device__ __forceinline__ u64 umax64(u64 a, u64 b) { return a < b ? b : a; }
__device__ __forceinline__ u32 redux_min(u32 v) {
    u32 r;
    asm("redux.sync.min.u32 %0, %1, 0xffffffff;" : "=r"(r) : "r"(v));
    return r;
}

// ---------------------------------------------------------------------------
// Kernel 1: cost matrix (row-major) + transposed copy to g_Ct.
// ---------------------------------------------------------------------------
__global__ void __launch_bounds__(256) cost_kernel(
    const float* __restrict__ logits,
    const float* __restrict__ pboxes,
    const int*   __restrict__ labels,
    const float* __restrict__ tboxes,
    float* __restrict__ Cout)
{
    const int b    = blockIdx.y;
    const int tid  = threadIdx.x;
    const int lane = tid & 31;
    const int wid  = tid >> 5;
    const int q0   = blockIdx.x * 16;

    __shared__ float4 s_tb[NT];
    __shared__ float4 s_tx[NT];
    __shared__ float  s_ta[NT];
    __shared__ int    s_lab[NT];
    __shared__ float  s_exp[8][92];
    __shared__ float  s_t[16][132];

    if (tid < NT) {
        const float* tb = tboxes + ((size_t)b * NT + tid) * 4;
        float cx = tb[0], cy = tb[1], w = tb[2], h = tb[3];
        s_tb[tid] = make_float4(cx, cy, w, h);
        float x0 = cx - 0.5f * w, y0 = cy - 0.5f * h;
        float x1 = cx + 0.5f * w, y1 = cy + 0.5f * h;
        s_tx[tid] = make_float4(x0, y0, x1, y1);
        s_ta[tid] = (x1 - x0) * (y1 - y0);
        s_lab[tid] = labels[b * NT + tid];
    }
    __syncthreads();

    #pragma unroll
    for (int rr = 0; rr < 2; rr++) {
        const int qi = rr * 8 + wid;
        const int q  = q0 + qi;
        if (q >= NQ) continue;

        const float* lr = logits + ((size_t)b * NQ + q) * NCLS;
        float l0 = lr[lane];
        float l1 = lr[lane + 32];
        float l2 = (lane + 64 < NCLS) ? lr[lane + 64] : -INFINITY;
        float m = fmaxf(fmaxf(l0, l1), l2);
        #pragma unroll
        for (int o = 16; o; o >>= 1) m = fmaxf(m, __shfl_xor_sync(0xffffffffu, m, o));
        float e0 = expf(l0 - m), e1 = expf(l1 - m);
        float e2 = (lane + 64 < NCLS) ? expf(l2 - m) : 0.0f;
        float ssum = e0 + e1 + e2;
        #pragma unroll
        for (int o = 16; o; o >>= 1) ssum += __shfl_xor_sync(0xffffffffu, ssum, o);
        s_exp[wid][lane] = e0;
        s_exp[wid][lane + 32] = e1;
        if (lane + 64 < NCLS) s_exp[wid][lane + 64] = e2;
        __syncwarp();
        float inv = 1.0f / ssum;

        const float* pbp = pboxes + ((size_t)b * NQ + q) * 4;
        float pcx = pbp[0], pcy = pbp[1], pw = pbp[2], ph = pbp[3];
        float px0 = pcx - 0.5f * pw, py0 = pcy - 0.5f * ph;
        float px1 = pcx + 0.5f * pw, py1 = pcy + 0.5f * ph;
        float pa  = (px1 - px0) * (py1 - py0);

        float cst[4];
        #pragma unroll
        for (int r = 0; r < 4; r++) {
            int t = (lane << 2) | r;
            float4 tb = s_tb[t];
            float4 tx = s_tx[t];
            float pl  = s_exp[wid][s_lab[t]] * inv;
            float l1c = fabsf(pcx - tb.x) + fabsf(pcy - tb.y)
                      + fabsf(pw - tb.z) + fabsf(ph - tb.w);
            float ix0 = fmaxf(px0, tx.x), iy0 = fmaxf(py0, tx.y);
            float ix1 = fminf(px1, tx.z), iy1 = fminf(py1, tx.w);
            float inter = fmaxf(ix1 - ix0, 0.0f) * fmaxf(iy1 - iy0, 0.0f);
            float uni   = pa + s_ta[t] - inter;
            float iou   = inter / uni;
            float cx0 = fminf(px0, tx.x), cy0 = fminf(py0, tx.y);
            float cx1 = fmaxf(px1, tx.z), cy1 = fmaxf(py1, tx.w);
            float ac  = fmaxf(cx1 - cx0, 0.0f) * fmaxf(cy1 - cy0, 0.0f);
            float giou = iou - (ac - uni) / ac;
            cst[r] = -pl + 5.0f * l1c - 2.0f * giou;
        }

        float* crow = Cout + ((size_t)b * NQ + q) * NT;
        *(float4*)(crow + (lane << 2)) = make_float4(cst[0], cst[1], cst[2], cst[3]);
        *(float4*)(&s_t[qi][lane << 2]) = make_float4(cst[0], cst[1], cst[2], cst[3]);
    }
    __syncthreads();

    {
        const int colg = tid >> 1;
        const int half = tid & 1;
        float v[8];
        #pragma unroll
        for (int k = 0; k < 8; k++) v[k] = s_t[half * 8 + k][colg];
        float* dst = g_Ct + ((size_t)b * NT + colg) * CTS + q0 + half * 8;
        *(float4*)(dst)     = make_float4(v[0], v[1], v[2], v[3]);
        *(float4*)(dst + 4) = make_float4(v[4], v[5], v[6], v[7]);
    }
}

// ---------------------------------------------------------------------------
// Kernel 2: greedy.  Per-column sorted top-16 lists in SMEM (layout [slot][col]),
// single-warp loop with register heads, redux-based argmin, coalesced
// transposed fallback rescans.
// ---------------------------------------------------------------------------
__global__ void __launch_bounds__(256) greedy_kernel(
    const float* __restrict__ Cmat,
    float* __restrict__ out)
{
    const int b    = blockIdx.x;
    const int tid  = threadIdx.x;
    const int lane = tid & 31;
    const int wid  = tid >> 5;
    const float* __restrict__ Cb = Cmat + (size_t)b * NQ * NT;
    const float* __restrict__ Ct = g_Ct + (size_t)b * NT * CTS;

    __shared__ u64 s_list[32][NT];     // [slot][col]; slots 0..15 asc, 16..31 desc
    __shared__ u32 s_rowdead[32];
    __shared__ int s_src[NT], s_tgt[NT];

    // ---- phase 1: top-16 of each half-column (256 threads) ----
    {
        const int c    = tid & 127;
        const int half = tid >> 7;
        const int q0   = half ? 448 : 0;
        const int q1   = half ? NQ  : 448;

        u64 lst[LK];
        #pragma unroll
        for (int s = 0; s < LK; s++) lst[s] = ~0ull;

        for (int qb = q0; qb < q1; qb += 16) {
            float v[16];
            #pragma unroll
            for (int x = 0; x < 16; x++) {
                int q = qb + x;
                v[x] = (q < q1) ? Cb[q * NT + c] : 0.0f;
            }
            #pragma unroll
            for (int x = 0; x < 16; x++) {
                int q = qb + x;
                if (q < q1) {
                    u64 k = ((u64)f2ord(v[x]) << 18) | ((u32)q << 8) | (u32)c;
                    if (k < lst[LK - 1]) {
                        lst[LK - 1] = k;
                        #pragma unroll
                        for (int s = LK - 1; s > 0; s--) {
                            u64 a = lst[s - 1], bb = lst[s];
                            lst[s - 1] = umin64(a, bb);
                            lst[s]     = umax64(a, bb);
                        }
                    }
                }
            }
        }
        if (half == 0) {
            #pragma unroll
            for (int s = 0; s < LK; s++) s_list[s][c] = lst[s];
        } else {
            #pragma unroll
            for (int s = 0; s < LK; s++) s_list[31 - s][c] = lst[s];
        }
    }
    if (tid < 32) s_rowdead[tid] = 0u;
    __syncthreads();

    // ---- phase 2: bitonic halver + merge -> sorted 16 smallest in slots 0..15 ----
    if (tid < NT) {
        const int c = tid;
        #pragma unroll
        for (int s = 0; s < 16; s++)
            s_list[s][c] = umin64(s_list[s][c], s_list[s + 16][c]);
        #pragma unroll
        for (int j = 8; j > 0; j >>= 1) {
            #pragma unroll
            for (int s = 0; s < 16; s++) {
                if ((s & j) == 0) {
                    u64 a = s_list[s][c], bb = s_list[s | j][c];
                    s_list[s][c]     = umin64(a, bb);
                    s_list[s | j][c] = umax64(a, bb);
                }
            }
        }
    }
    __syncthreads();

    // ---- phase 3: warp 0 runs the 128 sequential steps ----
    if (wid != 0) return;

    u64 ck[4];
    int pos[4];
    #pragma unroll
    for (int r = 0; r < 4; r++) {
        ck[r]  = s_list[0][r * 32 + lane];
        pos[r] = 1;
    }

    for (int t = 0; t < NT; t++) {
        // two-phase exact argmin via redux
        u64 h = umin64(umin64(ck[0], ck[1]), umin64(ck[2], ck[3]));
        u32 hi = (u32)(h >> 32);
        u32 minh = redux_min(hi);
        u32 lo = (hi == minh) ? (u32)h : 0xFFFFFFFFu;
        u32 minl = redux_min(lo);
        u64 m = ((u64)minh << 32) | minl;

        const int i = (int)((m >> 8) & 0x3FFu);
        const int j = (int)(m & 0xFFu);
        if (lane == 0) {
            s_src[t] = i;
            s_tgt[t] = j;
            s_rowdead[i >> 5] |= (1u << (i & 31));
        }
        if (t == NT - 1) break;

        u32 exh = 0;
        #pragma unroll
        for (int r = 0; r < 4; r++) {
            if (ck[r] == m) { ck[r] = ~0ull; continue; }
            if (ck[r] != ~0ull && (int)((ck[r] >> 8) & 0x3FFu) == i) {
                const int c = r * 32 + lane;
                int p = pos[r];
                bool found = false;
                while (p < LK) {
                    u64 e = s_list[p][c]; p++;
                    int q = (int)((e >> 8) & 0x3FFu);
                    if (q != i && !((s_rowdead[q >> 5] >> (q & 31)) & 1u)) {
                        ck[r] = e; pos[r] = p; found = true; break;
                    }
                }
                if (!found) { exh |= (1u << r); pos[r] = LK; }
            }
        }

        // fallback: coalesced rescan of the transposed column
        if (__ballot_sync(0xffffffffu, exh != 0)) {
            #pragma unroll
            for (int r = 0; r < 4; r++) {
                u32 mask = __ballot_sync(0xffffffffu, (exh >> r) & 1u);
                while (mask) {
                    const int sl = __ffs(mask) - 1;
                    mask &= mask - 1;
                    const int c = r * 32 + sl;
                    const float* col = Ct + (size_t)c * CTS;
                    u64 best = ~0ull;
                    #pragma unroll 4
                    for (int q = lane; q < NQ; q += 32) {
                        if (q == i) continue;
                        if ((s_rowdead[q >> 5] >> (q & 31)) & 1u) continue;
                        u64 k = ((u64)f2ord(col[q]) << 18) | ((u32)q << 8) | (u32)c;
                        best = umin64(best, k);
                    }
                    #pragma unroll
                    for (int o = 16; o; o >>= 1)
                        best = umin64(best, __shfl_xor_sync(0xffffffffu, best, o));
                    if (lane == sl) ck[r] = best;
                }
            }
        }
        __syncwarp();
    }

    __syncwarp();
    #pragma unroll
    for (int r = 0; r < 4; r++) {
        int t = r * 32 + lane;
        out[b * NT + t]           = (float)s_src[t];
        out[NB * NT + b * NT + t] = (float)s_tgt[t];
    }
}

// ---------------------------------------------------------------------------
extern "C" void kernel_launch(void* const* d_in, const int* in_sizes, int n_in,
                              void* d_out, int out_size) {
    const float* logits = (const float*)d_in[0];
    const float* pboxes = (const float*)d_in[1];
    const int*   labels = (const int*)d_in[2];
    const float* tboxes = (const float*)d_in[3];
    float* out = (float*)d_out;

    float* Cout = out + 2 * NB * NT;

    dim3 grid1((NQ + 15) / 16, NB);
    cost_kernel<<<grid1, 256>>>(logits, pboxes, labels, tboxes, Cout);

    greedy_kernel<<<NB, 256>>>(Cout, out);
}

// round 7
// speedup vs baseline: 1.3335x; 1.2865x over previous
#include <cuda_runtime.h>
#include <cuda_bf16.h>
#include <stdint.h>
#include <math.h>

#define NB   64
#define NQ   900
#define NT   128
#define NCLS 91
#define NSEG 32
#define SEGW 29     // NSEG*SEGW = 928 >= NQ
#define CTS  928    // transposed column stride

typedef unsigned long long u64;
typedef unsigned int       u32;

// Transposed cost copy: g_Ct[b][col][q] (column-contiguous; rows >= 900 never read)
__device__ float g_Ct[(size_t)NB * NT * CTS];
// Per-(batch, segment, column) minimum key, built by cost_kernel via atomicMin.
__device__ u64 g_segmin[(size_t)NB * NSEG * NT];

__device__ __forceinline__ u32 f2ord(float f) {
    u32 u = __float_as_uint(f);
    return (u & 0x80000000u) ? ~u : (u | 0x80000000u);
}
__device__ __forceinline__ u64 umin64(u64 a, u64 b) { return a < b ? a : b; }
__device__ __forceinline__ u32 redux_min(u32 v) {
    u32 r;
    asm("redux.sync.min.u32 %0, %1, 0xffffffff;" : "=r"(r) : "r"(v));
    return r;
}
// exact warp-wide u64 min (keys are unique)
__device__ __forceinline__ u64 wredmin(u64 k) {
    u32 hi = (u32)(k >> 32);
    u32 mh = redux_min(hi);
    u32 lo = (hi == mh) ? (u32)k : 0xFFFFFFFFu;
    u32 ml = redux_min(lo);
    return ((u64)mh << 32) | ml;
}

// ---------------------------------------------------------------------------
// Kernel 0: reset segment minima (graph-replay-safe deterministic init).
// ---------------------------------------------------------------------------
__global__ void __launch_bounds__(256) init_kernel() {
    const int b = blockIdx.x;
    for (int idx = threadIdx.x; idx < NSEG * NT; idx += 256)
        g_segmin[(size_t)b * NSEG * NT + idx] = ~0ull;
}

// ---------------------------------------------------------------------------
// Kernel 1: cost matrix (row-major to out) + transposed copy + segmin atomics.
// ---------------------------------------------------------------------------
__global__ void __launch_bounds__(256) cost_kernel(
    const float* __restrict__ logits,
    const float* __restrict__ pboxes,
    const int*   __restrict__ labels,
    const float* __restrict__ tboxes,
    float* __restrict__ Cout)
{
    const int b    = blockIdx.y;
    const int tid  = threadIdx.x;
    const int lane = tid & 31;
    const int wid  = tid >> 5;
    const int q0   = blockIdx.x * 16;

    __shared__ float4 s_tb[NT];
    __shared__ float4 s_tx[NT];
    __shared__ float  s_ta[NT];
    __shared__ int    s_lab[NT];
    __shared__ float  s_exp[8][92];
    __shared__ float  s_t[16][132];

    if (tid < NT) {
        const float* tb = tboxes + ((size_t)b * NT + tid) * 4;
        float cx = tb[0], cy = tb[1], w = tb[2], h = tb[3];
        s_tb[tid] = make_float4(cx, cy, w, h);
        float x0 = cx - 0.5f * w, y0 = cy - 0.5f * h;
        float x1 = cx + 0.5f * w, y1 = cy + 0.5f * h;
        s_tx[tid] = make_float4(x0, y0, x1, y1);
        s_ta[tid] = (x1 - x0) * (y1 - y0);
        s_lab[tid] = labels[b * NT + tid];
    }
    __syncthreads();

    #pragma unroll
    for (int rr = 0; rr < 2; rr++) {
        const int qi = rr * 8 + wid;
        const int q  = q0 + qi;
        if (q >= NQ) continue;   // s_t row stays garbage; guarded everywhere below

        const float* lr = logits + ((size_t)b * NQ + q) * NCLS;
        float l0 = lr[lane];
        float l1 = lr[lane + 32];
        float l2 = (lane + 64 < NCLS) ? lr[lane + 64] : -INFINITY;
        float m = fmaxf(fmaxf(l0, l1), l2);
        #pragma unroll
        for (int o = 16; o; o >>= 1) m = fmaxf(m, __shfl_xor_sync(0xffffffffu, m, o));
        float e0 = expf(l0 - m), e1 = expf(l1 - m);
        float e2 = (lane + 64 < NCLS) ? expf(l2 - m) : 0.0f;
        float ssum = e0 + e1 + e2;
        #pragma unroll
        for (int o = 16; o; o >>= 1) ssum += __shfl_xor_sync(0xffffffffu, ssum, o);
        s_exp[wid][lane] = e0;
        s_exp[wid][lane + 32] = e1;
        if (lane + 64 < NCLS) s_exp[wid][lane + 64] = e2;
        __syncwarp();
        float inv = 1.0f / ssum;

        const float* pbp = pboxes + ((size_t)b * NQ + q) * 4;
        float pcx = pbp[0], pcy = pbp[1], pw = pbp[2], ph = pbp[3];
        float px0 = pcx - 0.5f * pw, py0 = pcy - 0.5f * ph;
        float px1 = pcx + 0.5f * pw, py1 = pcy + 0.5f * ph;
        float pa  = (px1 - px0) * (py1 - py0);

        float cst[4];
        #pragma unroll
        for (int r = 0; r < 4; r++) {
            int t = (lane << 2) | r;
            float4 tb = s_tb[t];
            float4 tx = s_tx[t];
            float pl  = s_exp[wid][s_lab[t]] * inv;
            float l1c = fabsf(pcx - tb.x) + fabsf(pcy - tb.y)
                      + fabsf(pw - tb.z) + fabsf(ph - tb.w);
            float ix0 = fmaxf(px0, tx.x), iy0 = fmaxf(py0, tx.y);
            float ix1 = fminf(px1, tx.z), iy1 = fminf(py1, tx.w);
            float inter = fmaxf(ix1 - ix0, 0.0f) * fmaxf(iy1 - iy0, 0.0f);
            float uni   = pa + s_ta[t] - inter;
            float iou   = inter / uni;
            float cx0 = fminf(px0, tx.x), cy0 = fminf(py0, tx.y);
            float cx1 = fmaxf(px1, tx.z), cy1 = fmaxf(py1, tx.w);
            float ac  = fmaxf(cx1 - cx0, 0.0f) * fmaxf(cy1 - cy0, 0.0f);
            float giou = iou - (ac - uni) / ac;
            cst[r] = -pl + 5.0f * l1c - 2.0f * giou;
        }

        float* crow = Cout + ((size_t)b * NQ + q) * NT;
        *(float4*)(crow + (lane << 2)) = make_float4(cst[0], cst[1], cst[2], cst[3]);
        *(float4*)(&s_t[qi][lane << 2]) = make_float4(cst[0], cst[1], cst[2], cst[3]);
    }
    __syncthreads();

    // transpose + segmin atomics: thread -> (col = tid>>1, half = tid&1)
    {
        const int colg = tid >> 1;
        const int half = tid & 1;
        const int a    = q0 + half * 8;   // first row of this thread's 8
        float v[8];
        #pragma unroll
        for (int k = 0; k < 8; k++) v[k] = s_t[half * 8 + k][colg];

        float* dst = g_Ct + ((size_t)b * NT + colg) * CTS + a;
        *(float4*)(dst)     = make_float4(v[0], v[1], v[2], v[3]);
        *(float4*)(dst + 4) = make_float4(v[4], v[5], v[6], v[7]);

        // segment minima (rows a..a+7 span at most 2 segments)
        const int s0    = a / SEGW;
        const int split = (s0 + 1) * SEGW;
        u64 m0 = ~0ull, m1 = ~0ull;
        #pragma unroll
        for (int k = 0; k < 8; k++) {
            int q = a + k;
            if (q < NQ) {
                u64 key = ((u64)f2ord(v[k]) << 18) | ((u32)q << 8) | (u32)colg;
                if (q < split) m0 = umin64(m0, key);
                else           m1 = umin64(m1, key);
            }
        }
        u64* segb = g_segmin + (size_t)b * NSEG * NT;
        if (m0 != ~0ull) atomicMin(&segb[s0 * NT + colg], m0);
        if (m1 != ~0ull) atomicMin(&segb[(s0 + 1) * NT + colg], m1);
    }
}

// ---------------------------------------------------------------------------
// Kernel 2: greedy matching with SMEM segment-minima.  One block per batch.
// Each warp owns 16 columns; all warps compute the argmin redundantly;
// exactly one __syncthreads per step.
// ---------------------------------------------------------------------------
__global__ void __launch_bounds__(256) greedy_kernel(float* __restrict__ out)
{
    const int b    = blockIdx.x;
    const int tid  = threadIdx.x;
    const int lane = tid & 31;
    const int wid  = tid >> 5;
    const float* __restrict__ Ctb = g_Ct + (size_t)b * NT * CTS;

    __shared__ u64 segmin[NSEG][NT + 1];   // [seg][col], +1 pad for colmin reads
    __shared__ u64 colkey[NT];
    __shared__ u32 rowdead[32];
    __shared__ int s_src[NT], s_tgt[NT];

    // load segmins (coalesced 32KB)
    {
        const u64* __restrict__ segb = g_segmin + (size_t)b * NSEG * NT;
        for (int idx = tid; idx < NSEG * NT; idx += 256)
            segmin[idx >> 7][idx & 127] = segb[idx];
    }
    if (tid < 32) rowdead[tid] = 0u;
    __syncthreads();

    if (tid < NT) {
        u64 m = ~0ull;
        #pragma unroll
        for (int s = 0; s < NSEG; s++) m = umin64(m, segmin[s][tid]);
        colkey[tid] = m;
    }
    __syncthreads();

    for (int t = 0; t < NT; t++) {
        // ---- argmin (replicated in every warp; identical result) ----
        u64 h = umin64(umin64(colkey[lane], colkey[lane + 32]),
                       umin64(colkey[lane + 64], colkey[lane + 96]));
        u64 m = wredmin(h);
        const int i = (int)((m >> 8) & 0x3FFu);
        const int j = (int)(m & 0xFFu);

        if (tid == 0) {
            s_src[t] = i;
            s_tgt[t] = j;
            colkey[j] = ~0ull;
            rowdead[i >> 5] |= (1u << (i & 31));
        }
        if (t == NT - 1) break;

        const int si = i / SEGW;

        // ---- dirty detection: warp w owns columns 16w..16w+15 ----
        bool dirty = false;
        if (lane < 16) {
            const int c = (wid << 4) + lane;
            if (c != j && colkey[c] != ~0ull)
                dirty = ((int)((segmin[si][c] >> 8) & 0x3FFu) == i);
        }
        u32 mask = __ballot_sync(0xffffffffu, dirty);

        while (mask) {
            const int sl = __ffs(mask) - 1;
            mask &= mask - 1;
            const int c2 = (wid << 4) + sl;

            // rescan segment si of column c2 (29 contiguous floats, L2)
            const int q = si * SEGW + lane;
            u64 key = ~0ull;
            if (lane < SEGW && q < NQ) {
                if (q != i && !((rowdead[q >> 5] >> (q & 31)) & 1u)) {
                    float v = Ctb[(size_t)c2 * CTS + q];
                    key = ((u64)f2ord(v) << 18) | ((u32)q << 8) | (u32)c2;
                }
            }
            u64 nk = wredmin(key);
            if (lane == 0) segmin[si][c2] = nk;
            __syncwarp();

            // recompute column min over its 32 segment minima
            u64 sv = segmin[lane][c2];
            u64 nc = wredmin(sv);
            if (lane == 0) colkey[c2] = nc;
        }
        __syncthreads();
    }

    __syncthreads();
    if (tid < NT) {
        out[b * NT + tid]           = (float)s_src[tid];
        out[NB * NT + b * NT + tid] = (float)s_tgt[tid];
    }
}

// ---------------------------------------------------------------------------
extern "C" void kernel_launch(void* const* d_in, const int* in_sizes, int n_in,
                              void* d_out, int out_size) {
    const float* logits = (const float*)d_in[0];
    const float* pboxes = (const float*)d_in[1];
    const int*   labels = (const int*)d_in[2];
    const float* tboxes = (const float*)d_in[3];
    float* out = (float*)d_out;

    float* Cout = out + 2 * NB * NT;

    init_kernel<<<NB, 256>>>();
    dim3 grid1((NQ + 15) / 16, NB);
    cost_kernel<<<grid1, 256>>>(logits, pboxes, labels, tboxes, Cout);
    greedy_kernel<<<NB, 256>>>(out);
}